// round 17
// baseline (speedup 1.0000x reference)
#include <cuda_runtime.h>
#include <cuda_bf16.h>

// 3x3 stride-2 VALID average pooling, fp32.
// x: (8, 64, 512, 512) -> out: (8, 64, 255, 255)
//
// Register-rolling, barrier-free + full streaming cache policy:
//  - ld.global.cs on the bulk float4 row loads (read-once stream; evict-first
//    still fills L1/L2 so the short-distance overlap-scalar and strip-boundary
//    reuse both survive).
//  - st.global.cs scalar output stores (output never re-read; row stride 255
//    is odd so STG.64 would be misaligned every other row -> scalar only).
//  - __launch_bounds__(128, 8): 64-reg budget so ptxas front-batches LDG.128s.
// Traffic is provably minimal (653 MB measured vs 670 MB ideal).

#define IN_H 512
#define IN_W 512
#define OUT_H 255
#define OUT_W 255
#define RPB 15          // output rows per CTA (255 = 15 * 17, exact)
#define STRIPS 17
#define NT 128          // 128 threads x 2 cols = 256 >= 255 cols

__device__ __forceinline__ void stcs(float* p, float v) {
    asm volatile("st.global.cs.f32 [%0], %1;" :: "l"(p), "f"(v) : "memory");
}

__device__ __forceinline__ float4 ldcs4(const float4* p) {
    float4 v;
    asm volatile("ld.global.cs.v4.f32 {%0,%1,%2,%3}, [%4];"
                 : "=f"(v.x), "=f"(v.y), "=f"(v.z), "=f"(v.w) : "l"(p));
    return v;
}

__global__ __launch_bounds__(NT, 8)
void KeyedAvgpool2d_2413771620972_kernel(const float* __restrict__ x,
                                         float* __restrict__ out)
{
    const int rb = blockIdx.x;    // strip within plane (fast axis: boundary-row L2 reuse)
    const int nc = blockIdx.y;    // plane (N*C)
    const int t  = threadIdx.x;

    const float*  __restrict__ plane = x + (size_t)nc * IN_H * IN_W;
    const float4* __restrict__ p4    = reinterpret_cast<const float4*>(plane);

    const bool full = (t < NT - 1);   // t==127: ow1=255 invalid, elem 4t+4=512 OOB
    const int  oh0  = rb * RPB;
    const float inv9 = 1.0f / 9.0f;

    // Carried horizontal pair-sums of input row 2*oh0 (shared top row).
    float a_c, b_c;
    {
        const int ih = 2 * oh0;
        float4 v = ldcs4(p4 + (size_t)ih * (IN_W / 4) + t);
        float  e = full ? plane[(size_t)ih * IN_W + 4 * t + 4] : 0.0f;
        a_c = v.x + v.y + v.z;        // cols 4t..4t+2  -> output 2t
        b_c = v.z + v.w + e;          // cols 4t+2..4t+4 -> output 2t+1
    }

    float* __restrict__ op =
        out + (size_t)nc * OUT_H * OUT_W + (size_t)oh0 * OUT_W + 2 * t;

    #pragma unroll
    for (int r = 0; r < RPB; r++) {
        const int ih1 = 2 * (oh0 + r) + 1;

        // Two fresh input rows per output row (read-once property).
        float4 v1 = ldcs4(p4 + (size_t)ih1 * (IN_W / 4) + t);
        float4 v2 = ldcs4(p4 + (size_t)(ih1 + 1) * (IN_W / 4) + t);
        float  e1 = full ? plane[(size_t)ih1 * IN_W + 4 * t + 4] : 0.0f;
        float  e2 = full ? plane[(size_t)(ih1 + 1) * IN_W + 4 * t + 4] : 0.0f;

        const float a1 = v1.x + v1.y + v1.z, b1 = v1.z + v1.w + e1;
        const float a2 = v2.x + v2.y + v2.z, b2 = v2.z + v2.w + e2;

        stcs(op, (a_c + a1 + a2) * inv9);
        if (full) stcs(op + 1, (b_c + b1 + b2) * inv9);

        a_c = a2;                     // bottom row becomes next top row
        b_c = b2;
        op += OUT_W;
    }
}

extern "C" void kernel_launch(void* const* d_in, const int* in_sizes, int n_in,
                              void* d_out, int out_size)
{
    const float* x = (const float*)d_in[0];
    float* out = (float*)d_out;

    dim3 grid(STRIPS, in_sizes[0] / (IN_H * IN_W));   // 17 x 512
    KeyedAvgpool2d_2413771620972_kernel<<<grid, NT>>>(x, out);
}